// round 10
// baseline (speedup 1.0000x reference)
#include <cuda_runtime.h>
#include <cuda_bf16.h>
#include <cstdint>

// Swin shifted-window MSA. B=4, H=W=256, C=192, WS=8, SHIFT=4, heads=6, hd=32.
#define QKV_STRIDE 50331648ull
#define ATTN_ELEMS 50331648ull
typedef unsigned long long ULL;

__device__ float g_qkv[3ull * QKV_STRIDE];   // [which][win*6+head][p=64][d=32]
__device__ float g_attn[ATTN_ELEMS];         // [win][p][c=192]

// Pre-converted weights, [n][k] bf16, hi/lo planes.
__device__ __nv_bfloat16 g_wq_hi[576 * 192];
__device__ __nv_bfloat16 g_wq_lo[576 * 192];
__device__ __nv_bfloat16 g_wl_hi[192 * 192];
__device__ __nv_bfloat16 g_wl_lo[192 * 192];

// ---------------- f32x2 helpers --------------------------------------------
__device__ __forceinline__ ULL fma2(ULL a, ULL b, ULL c) {
    ULL d; asm("fma.rn.f32x2 %0, %1, %2, %3;" : "=l"(d) : "l"(a), "l"(b), "l"(c));
    return d;
}
__device__ __forceinline__ ULL pack2(float x, float y) {
    ULL d; asm("mov.b64 %0, {%1, %2};" : "=l"(d) : "f"(x), "f"(y)); return d;
}
__device__ __forceinline__ float lo2(ULL v) {
    float x, y; asm("mov.b64 {%0, %1}, %2;" : "=f"(x), "=f"(y) : "l"(v)); return x;
}
__device__ __forceinline__ float hi2(ULL v) {
    float x, y; asm("mov.b64 {%0, %1}, %2;" : "=f"(x), "=f"(y) : "l"(v)); return y;
}

// ---------------- mma.sync / cp.async helpers ------------------------------
__device__ __forceinline__ uint32_t smem_u32(const void* p) {
    uint32_t a;
    asm("{ .reg .u64 t; cvta.to.shared.u64 t, %1; cvt.u32.u64 %0, t; }"
        : "=r"(a) : "l"(p));
    return a;
}
#define LDM4(r, addr) \
    asm volatile("ldmatrix.sync.aligned.m8n8.x4.shared.b16 {%0,%1,%2,%3}, [%4];" \
        : "=r"((r)[0]), "=r"((r)[1]), "=r"((r)[2]), "=r"((r)[3]) : "r"(addr))
#define MMA16816(c, a, b) \
    asm volatile("mma.sync.aligned.m16n8k16.row.col.f32.bf16.bf16.f32 " \
        "{%0,%1,%2,%3}, {%4,%5,%6,%7}, {%8,%9}, {%0,%1,%2,%3};" \
        : "+f"((c)[0]), "+f"((c)[1]), "+f"((c)[2]), "+f"((c)[3]) \
        : "r"((a)[0]), "r"((a)[1]), "r"((a)[2]), "r"((a)[3]), \
          "r"((b)[0]), "r"((b)[1]))
#define CP16(dst, src) \
    asm volatile("cp.async.ca.shared.global [%0], [%1], 16;" \
        :: "r"(dst), "l"(src))
#define CP_COMMIT() asm volatile("cp.async.commit_group;" ::: "memory")
#define CP_WAIT1()  asm volatile("cp.async.wait_group 1;" ::: "memory")
#define CP_WAIT0()  asm volatile("cp.async.wait_group 0;" ::: "memory")

// SMEM layout (bytes). Rows padded to 400B (200 bf16) -> conflict-free ldmatrix.
#define ROWB 400
#define SA_HI 0
#define SA_LO 51200
#define S_B   102400
#define B_BUF 51200
#define SMEM_SZ 204800

__device__ __forceinline__ void split_store4p(char* hi, char* lo, float4 v) {
    __nv_bfloat16 h0 = __float2bfloat16(v.x);
    __nv_bfloat16 h1 = __float2bfloat16(v.y);
    __nv_bfloat16 h2 = __float2bfloat16(v.z);
    __nv_bfloat16 h3 = __float2bfloat16(v.w);
    __nv_bfloat16 l0 = __float2bfloat16(v.x - __bfloat162float(h0));
    __nv_bfloat16 l1 = __float2bfloat16(v.y - __bfloat162float(h1));
    __nv_bfloat16 l2 = __float2bfloat16(v.z - __bfloat162float(h2));
    __nv_bfloat16 l3 = __float2bfloat16(v.w - __bfloat162float(h3));
    reinterpret_cast<__nv_bfloat162*>(hi)[0] = __nv_bfloat162(h0, h1);
    reinterpret_cast<__nv_bfloat162*>(hi)[1] = __nv_bfloat162(h2, h3);
    reinterpret_cast<__nv_bfloat162*>(lo)[0] = __nv_bfloat162(l0, l1);
    reinterpret_cast<__nv_bfloat162*>(lo)[1] = __nv_bfloat162(l2, l3);
}

// cp.async one B slice (64 n x 192 k bf16, hi+lo) into dstbase. 512 threads.
__device__ __forceinline__ void stage_b_async(
    uint32_t dstbase, const __nv_bfloat16* hi, const __nv_bfloat16* lo,
    int n0, int t)
{
#pragma unroll
    for (int plane = 0; plane < 2; plane++) {
        const __nv_bfloat16* src = plane ? lo : hi;
        const uint32_t dplane = dstbase + plane * 25600u;
#pragma unroll
        for (int c = 0; c < 3; c++) {
            const int chunk = c * 512 + t;          // 0..1535
            const int row = chunk / 24;
            const int ck  = chunk % 24;
            CP16(dplane + (uint32_t)row * ROWB + ck * 16,
                 src + ((size_t)(n0 + row)) * 192 + ck * 8);
        }
    }
}

// Per-warp 32x16 sub-tile of D(128x64): 3-term split-bf16 MMA from smem.
__device__ __forceinline__ void gemm_body(const uint32_t sbase, uint32_t bbase,
                                          int lane, int m_base, int n_base,
                                          float acc[2][2][4]) {
    const uint32_t aoff = (uint32_t)(m_base + (lane & 15)) * ROWB +
                          (uint32_t)(lane >> 4) * 16;
    const uint32_t a_hi = sbase + SA_HI + aoff;
    const uint32_t a_lo = sbase + SA_LO + aoff;
    const uint32_t boff =
        (uint32_t)(n_base + (lane & 7) + (((lane >> 4) & 1) << 3)) * ROWB +
        (uint32_t)((lane >> 3) & 1) * 16;
    const uint32_t b_hi = bbase + boff;
    const uint32_t b_lo = bbase + 25600u + boff;

#pragma unroll
    for (int ks = 0; ks < 12; ks++) {
        const uint32_t kb = ks * 32;
        uint32_t ah[2][4], al[2][4], bh[4], bl[4];
        LDM4(ah[0], a_hi + kb);
        LDM4(ah[1], a_hi + 16 * ROWB + kb);
        LDM4(al[0], a_lo + kb);
        LDM4(al[1], a_lo + 16 * ROWB + kb);
        LDM4(bh, b_hi + kb);
        LDM4(bl, b_lo + kb);
#pragma unroll
        for (int mi = 0; mi < 2; mi++) {
#pragma unroll
            for (int ni = 0; ni < 2; ni++) {
                uint32_t bfh[2] = {bh[ni * 2], bh[ni * 2 + 1]};
                uint32_t bfl[2] = {bl[ni * 2], bl[ni * 2 + 1]};
                MMA16816(acc[mi][ni], ah[mi], bfh);
                MMA16816(acc[mi][ni], al[mi], bfh);
                MMA16816(acc[mi][ni], ah[mi], bfl);
            }
        }
    }
}

// ---------------------------------------------------------------------------
// Kernel 0: weight pre-conversion into [n][k] bf16 hi/lo planes.
// ---------------------------------------------------------------------------
__global__ __launch_bounds__(256) void k_prep(
    const float* __restrict__ wq, const float* __restrict__ wl)
{
    const int idx = blockIdx.x * 256 + threadIdx.x;
    if (idx < 576 * 192) {
        const int n = idx / 192, k = idx - n * 192;
        const float v = wq[(size_t)k * 576 + n];
        const __nv_bfloat16 h = __float2bfloat16(v);
        g_wq_hi[idx] = h;
        g_wq_lo[idx] = __float2bfloat16(v - __bfloat162float(h));
    }
    if (idx < 192 * 192) {
        const int n = idx / 192, k = idx - n * 192;
        const float v = wl[(size_t)k * 192 + n];
        const __nv_bfloat16 h = __float2bfloat16(v);
        g_wl_hi[idx] = h;
        g_wl_lo[idx] = __float2bfloat16(v - __bfloat162float(h));
    }
}

// ---------------------------------------------------------------------------
// Kernel 1: QKV projection. Grid (2048), 512 threads (16 warps, 4x4 grid).
// ---------------------------------------------------------------------------
__global__ __launch_bounds__(512) void k_qkv(
    const float* __restrict__ x, const float* __restrict__ bias)
{
    extern __shared__ char sm[];
    const uint32_t sbase = smem_u32(sm);
    const int t    = threadIdx.x;
    const int lane = t & 31;
    const int wid  = t >> 5;
    const int mt   = blockIdx.x;

    stage_b_async(sbase + S_B, g_wq_hi, g_wq_lo, 0, t);
    CP_COMMIT();

    // --- stage A (128 tokens x 192 ch), shift fused, split hi/lo
    for (int idx4 = t; idx4 < 6144; idx4 += 512) {
        const int m  = idx4 / 48;
        const int k4 = idx4 % 48;
        const int win = mt * 2 + (m >> 6);
        const int b  = win >> 10, wy = (win >> 5) & 31, wx = win & 31;
        const int p  = m & 63;
        const int shh = ((wy << 3) + (p >> 3) + 4) & 255;
        const int sww = ((wx << 3) + (p & 7) + 4) & 255;
        const float4 v = *reinterpret_cast<const float4*>(
            x + ((((size_t)b << 8) + shh) * 256 + sww) * 192 + k4 * 4);
        const uint32_t off = (uint32_t)m * ROWB + k4 * 8;
        split_store4p(sm + SA_HI + off, sm + SA_LO + off, v);
    }

    const int m_base = (wid >> 2) * 32;
    const int n_base = (wid & 3) * 16;
    const int lane4 = lane >> 2;
    const int lane2 = (lane & 3) * 2;

    for (int nt = 0; nt < 9; nt++) {
        __syncthreads();
        if (nt < 8) {
            stage_b_async(sbase + S_B + ((nt + 1) & 1) * B_BUF,
                          g_wq_hi, g_wq_lo, (nt + 1) * 64, t);
            CP_COMMIT();
            CP_WAIT1();
        } else {
            CP_WAIT0();
        }
        __syncthreads();

        float acc[2][2][4] = {};
        gemm_body(sbase, sbase + S_B + (nt & 1) * B_BUF,
                  lane, m_base, n_base, acc);

        const int n0 = nt * 64;
#pragma unroll
        for (int mi = 0; mi < 2; mi++) {
            const int r  = m_base + mi * 16 + lane4;
            const int r2 = r + 8;
            const int win = mt * 2 + (r >> 6);
            const int p  = r & 63;
            const int p2 = r2 & 63;
#pragma unroll
            for (int ni = 0; ni < 2; ni++) {
                const int ng = n0 + n_base + ni * 8 + lane2;
                const int which = ng / 192;
                const int rr = ng - which * 192;
                const int head = rr >> 5;
                const int d = rr & 31;
                const float2 bb = *reinterpret_cast<const float2*>(bias + ng);
                float* gq = g_qkv + (size_t)which * QKV_STRIDE +
                            ((size_t)win * 6 + head) * 2048 + d;
                *reinterpret_cast<float2*>(gq + (size_t)p * 32) =
                    make_float2(acc[mi][ni][0] + bb.x, acc[mi][ni][1] + bb.y);
                *reinterpret_cast<float2*>(gq + (size_t)p2 * 32) =
                    make_float2(acc[mi][ni][2] + bb.x, acc[mi][ni][3] + bb.y);
            }
        }
    }
}

// ---------------------------------------------------------------------------
// Kernel 2: windowed attention (FFMA2). Grid (6144), 256 threads =
// 4 (win,head) pairs per block; dynamic smem 64KB.
// ---------------------------------------------------------------------------
__global__ __launch_bounds__(256) void k_attn(const float* __restrict__ rel_pos)
{
    extern __shared__ float smf[];
    const int t    = threadIdx.x;
    const int grp  = t >> 6;                 // 0..3
    const int p    = t & 63;
    const int pair = blockIdx.x * 4 + grp;   // win*6 + head
    const int win  = pair / 6;
    const int head = pair - win * 6;
    const int wy = (win >> 5) & 31;
    const int wx = win & 31;

    float* Ks = smf + grp * 4096;            // [64][32]
    float* Vs = Ks + 2048;

    const size_t base = (size_t)pair * 2048;
    const float* qb = g_qkv + base;
    const float* kb = g_qkv + QKV_STRIDE + base;
    const float* vb = g_qkv + 2 * QKV_STRIDE + base;

    ULL q2[16];
#pragma unroll
    for (int u = 0; u < 8; u++) {
        const ulonglong2 qv =
            *reinterpret_cast<const ulonglong2*>(qb + p * 32 + u * 4);
        q2[2 * u] = qv.x; q2[2 * u + 1] = qv.y;
        *reinterpret_cast<float4*>(Ks + p * 32 + u * 4) =
            *reinterpret_cast<const float4*>(kb + p * 32 + u * 4);
        *reinterpret_cast<float4*>(Vs + p * 32 + u * 4) =
            *reinterpret_cast<const float4*>(vb + p * 32 + u * 4);
    }
    __syncthreads();

    const int y1 = p >> 3, x1 = p & 7;
    const bool lastR = (wy == 31);
    const bool lastC = (wx == 31);

    float sc[64];
    float mx = -1e30f;
#pragma unroll 4
    for (int j = 0; j < 64; j++) {
        ULL s2a = 0ull, s2b = 0ull;
        const ulonglong2* kp = reinterpret_cast<const ulonglong2*>(Ks + j * 32);
#pragma unroll
        for (int u = 0; u < 8; u++) {
            const ulonglong2 kv = kp[u];
            s2a = fma2(q2[2 * u], kv.x, s2a);
            s2b = fma2(q2[2 * u + 1], kv.y, s2b);
        }
        float s = (lo2(s2a) + hi2(s2a)) + (lo2(s2b) + hi2(s2b));
        s *= 0.1767766953f;
        const int y2 = j >> 3, x2 = j & 7;
        s += rel_pos[((y1 - y2 + 7) * 15 + (x1 - x2 + 7)) * 6 + head];
        const bool bad = (lastR && ((y1 < 4) != (y2 < 4))) ||
                         (lastC && ((x1 < 4) != (x2 < 4)));
        if (bad) s = -1e30f;
        sc[j] = s;
        mx = fmaxf(mx, s);
    }
    float sum = 0.f;
#pragma unroll 4
    for (int j = 0; j < 64; j++) { sc[j] = __expf(sc[j] - mx); sum += sc[j]; }
    const float inv = 1.f / sum;

    ULL out2[16];
#pragma unroll
    for (int u = 0; u < 16; u++) out2[u] = 0ull;
#pragma unroll 4
    for (int j = 0; j < 64; j++) {
        const ULL wj = pack2(sc[j], sc[j]);
        const ulonglong2* vp = reinterpret_cast<const ulonglong2*>(Vs + j * 32);
#pragma unroll
        for (int u = 0; u < 8; u++) {
            const ulonglong2 vv = vp[u];
            out2[2 * u]     = fma2(wj, vv.x, out2[2 * u]);
            out2[2 * u + 1] = fma2(wj, vv.y, out2[2 * u + 1]);
        }
    }

    float* ob = g_attn + ((size_t)win * 64 + p) * 192 + head * 32;
#pragma unroll
    for (int u = 0; u < 8; u++) {
        float4 st;
        st.x = lo2(out2[2 * u])     * inv;
        st.y = hi2(out2[2 * u])     * inv;
        st.z = lo2(out2[2 * u + 1]) * inv;
        st.w = hi2(out2[2 * u + 1]) * inv;
        *reinterpret_cast<float4*>(ob + u * 4) = st;
    }
}

// ---------------------------------------------------------------------------
// Kernel 3: output projection. Grid (2048), 512 threads, loops 3 n-tiles.
// ---------------------------------------------------------------------------
__global__ __launch_bounds__(512) void k_proj(
    const float* __restrict__ bias, float* __restrict__ out)
{
    extern __shared__ char sm[];
    const uint32_t sbase = smem_u32(sm);
    const int t    = threadIdx.x;
    const int lane = t & 31;
    const int wid  = t >> 5;
    const int mt   = blockIdx.x;

    stage_b_async(sbase + S_B, g_wl_hi, g_wl_lo, 0, t);
    CP_COMMIT();

    const float* abase = g_attn + (size_t)mt * 128 * 192;
    for (int idx4 = t; idx4 < 6144; idx4 += 512) {
        const int m  = idx4 / 48;
        const int k4 = idx4 % 48;
        const float4 v = *reinterpret_cast<const float4*>(abase + m * 192 + k4 * 4);
        const uint32_t off = (uint32_t)m * ROWB + k4 * 8;
        split_store4p(sm + SA_HI + off, sm + SA_LO + off, v);
    }

    const int m_base = (wid >> 2) * 32;
    const int n_base = (wid & 3) * 16;
    const int lane4 = lane >> 2;
    const int lane2 = (lane & 3) * 2;

    for (int nt = 0; nt < 3; nt++) {
        __syncthreads();
        if (nt < 2) {
            stage_b_async(sbase + S_B + ((nt + 1) & 1) * B_BUF,
                          g_wl_hi, g_wl_lo, (nt + 1) * 64, t);
            CP_COMMIT();
            CP_WAIT1();
        } else {
            CP_WAIT0();
        }
        __syncthreads();

        float acc[2][2][4] = {};
        gemm_body(sbase, sbase + S_B + (nt & 1) * B_BUF,
                  lane, m_base, n_base, acc);

        const int n0 = nt * 64;
#pragma unroll
        for (int mi = 0; mi < 2; mi++) {
#pragma unroll
            for (int half = 0; half < 2; half++) {
                const int r = m_base + mi * 16 + half * 8 + lane4;
                const int win = mt * 2 + (r >> 6);
                const int b  = win >> 10;
                const int wy = (win >> 5) & 31;
                const int wx = win & 31;
                const int p  = r & 63;
                const int oh = ((wy << 3) + (p >> 3) + 4) & 255;
                const int ow = ((wx << 3) + (p & 7) + 4) & 255;
                float* orow = out + ((((size_t)b << 8) + oh) * 256 + ow) * 192;
#pragma unroll
                for (int ni = 0; ni < 2; ni++) {
                    const int ng = n0 + n_base + ni * 8 + lane2;
                    const float2 bb = *reinterpret_cast<const float2*>(bias + ng);
                    float2 st;
                    st.x = acc[mi][ni][half * 2 + 0] + bb.x;
                    st.y = acc[mi][ni][half * 2 + 1] + bb.y;
                    *reinterpret_cast<float2*>(orow + ng) = st;
                }
            }
        }
    }
}

// ---------------------------------------------------------------------------
extern "C" void kernel_launch(void* const* d_in, const int* in_sizes, int n_in,
                              void* d_out, int out_size)
{
    const float* x     = (const float*)d_in[0];
    const float* w_qkv = (const float*)d_in[1];
    const float* b_qkv = (const float*)d_in[2];
    const float* w_lin = (const float*)d_in[3];
    const float* b_lin = (const float*)d_in[4];
    const float* rel   = (const float*)d_in[5];
    float* out = (float*)d_out;

    cudaFuncSetAttribute(k_qkv, cudaFuncAttributeMaxDynamicSharedMemorySize, SMEM_SZ);
    cudaFuncSetAttribute(k_proj, cudaFuncAttributeMaxDynamicSharedMemorySize, SMEM_SZ);
    cudaFuncSetAttribute(k_attn, cudaFuncAttributeMaxDynamicSharedMemorySize, 65536);

    k_prep<<<432, 256>>>(w_qkv, w_lin);
    k_qkv <<<2048, 512, SMEM_SZ>>>(x, b_qkv);
    k_attn<<<6144, 256, 65536>>>(rel);
    k_proj<<<2048, 512, SMEM_SZ>>>(b_lin, out);
}

// round 11
// speedup vs baseline: 1.0561x; 1.0561x over previous
#include <cuda_runtime.h>
#include <cuda_bf16.h>
#include <cstdint>

// Swin shifted-window MSA. B=4, H=W=256, C=192, WS=8, SHIFT=4, heads=6, hd=32.
#define QKV_STRIDE 50331648ull
#define ATTN_ELEMS 50331648ull
typedef unsigned long long ULL;

__device__ float g_qkv[3ull * QKV_STRIDE];   // [which][win*6+head][p=64][d=32]
__device__ float g_attn[ATTN_ELEMS];         // [win][p][c=192]

// Pre-converted weights, [n][k] bf16, hi/lo planes.
__device__ __nv_bfloat16 g_wq_hi[576 * 192];
__device__ __nv_bfloat16 g_wq_lo[576 * 192];
__device__ __nv_bfloat16 g_wl_hi[192 * 192];
__device__ __nv_bfloat16 g_wl_lo[192 * 192];

// ---------------- f32x2 helpers --------------------------------------------
__device__ __forceinline__ ULL fma2(ULL a, ULL b, ULL c) {
    ULL d; asm("fma.rn.f32x2 %0, %1, %2, %3;" : "=l"(d) : "l"(a), "l"(b), "l"(c));
    return d;
}
__device__ __forceinline__ ULL pack2(float x, float y) {
    ULL d; asm("mov.b64 %0, {%1, %2};" : "=l"(d) : "f"(x), "f"(y)); return d;
}
__device__ __forceinline__ float lo2(ULL v) {
    float x, y; asm("mov.b64 {%0, %1}, %2;" : "=f"(x), "=f"(y) : "l"(v)); return x;
}
__device__ __forceinline__ float hi2(ULL v) {
    float x, y; asm("mov.b64 {%0, %1}, %2;" : "=f"(x), "=f"(y) : "l"(v)); return y;
}

// ---------------- mma.sync / cp.async helpers ------------------------------
__device__ __forceinline__ uint32_t smem_u32(const void* p) {
    uint32_t a;
    asm("{ .reg .u64 t; cvta.to.shared.u64 t, %1; cvt.u32.u64 %0, t; }"
        : "=r"(a) : "l"(p));
    return a;
}
#define LDM4(r, addr) \
    asm volatile("ldmatrix.sync.aligned.m8n8.x4.shared.b16 {%0,%1,%2,%3}, [%4];" \
        : "=r"((r)[0]), "=r"((r)[1]), "=r"((r)[2]), "=r"((r)[3]) : "r"(addr))
#define MMA16816(c, a, b) \
    asm volatile("mma.sync.aligned.m16n8k16.row.col.f32.bf16.bf16.f32 " \
        "{%0,%1,%2,%3}, {%4,%5,%6,%7}, {%8,%9}, {%0,%1,%2,%3};" \
        : "+f"((c)[0]), "+f"((c)[1]), "+f"((c)[2]), "+f"((c)[3]) \
        : "r"((a)[0]), "r"((a)[1]), "r"((a)[2]), "r"((a)[3]), \
          "r"((b)[0]), "r"((b)[1]))
#define CP16(dst, src) \
    asm volatile("cp.async.ca.shared.global [%0], [%1], 16;" \
        :: "r"(dst), "l"(src))
#define CP_COMMIT() asm volatile("cp.async.commit_group;" ::: "memory")
#define CP_WAIT1()  asm volatile("cp.async.wait_group 1;" ::: "memory")
#define CP_WAIT0()  asm volatile("cp.async.wait_group 0;" ::: "memory")

// SMEM layout (bytes). Rows padded to 400B (200 bf16) -> conflict-free ldmatrix.
#define ROWB 400
#define SA_HI 0
#define SA_LO 51200
#define S_B   102400
#define B_BUF 51200
#define SMEM_SZ 204800

__device__ __forceinline__ void split_store4p(char* hi, char* lo, float4 v) {
    __nv_bfloat16 h0 = __float2bfloat16(v.x);
    __nv_bfloat16 h1 = __float2bfloat16(v.y);
    __nv_bfloat16 h2 = __float2bfloat16(v.z);
    __nv_bfloat16 h3 = __float2bfloat16(v.w);
    __nv_bfloat16 l0 = __float2bfloat16(v.x - __bfloat162float(h0));
    __nv_bfloat16 l1 = __float2bfloat16(v.y - __bfloat162float(h1));
    __nv_bfloat16 l2 = __float2bfloat16(v.z - __bfloat162float(h2));
    __nv_bfloat16 l3 = __float2bfloat16(v.w - __bfloat162float(h3));
    reinterpret_cast<__nv_bfloat162*>(hi)[0] = __nv_bfloat162(h0, h1);
    reinterpret_cast<__nv_bfloat162*>(hi)[1] = __nv_bfloat162(h2, h3);
    reinterpret_cast<__nv_bfloat162*>(lo)[0] = __nv_bfloat162(l0, l1);
    reinterpret_cast<__nv_bfloat162*>(lo)[1] = __nv_bfloat162(l2, l3);
}

// cp.async one B slice (64 n x 192 k bf16, hi+lo) into dstbase. 256 threads.
__device__ __forceinline__ void stage_b_async(
    uint32_t dstbase, const __nv_bfloat16* hi, const __nv_bfloat16* lo,
    int n0, int t)
{
#pragma unroll
    for (int plane = 0; plane < 2; plane++) {
        const __nv_bfloat16* src = plane ? lo : hi;
        const uint32_t dplane = dstbase + plane * 25600u;
#pragma unroll
        for (int c = 0; c < 6; c++) {
            const int chunk = c * 256 + t;          // 0..1535
            const int row = chunk / 24;
            const int ck  = chunk % 24;
            CP16(dplane + (uint32_t)row * ROWB + ck * 16,
                 src + ((size_t)(n0 + row)) * 192 + ck * 8);
        }
    }
}

// Per-warp 32x32 sub-tile of D(128x64): 3-term split-bf16 MMA from smem,
// with fragment double-buffering (load ks+1 before MMAs of ks).
__device__ __forceinline__ void gemm_body(const uint32_t sbase, uint32_t bbase,
                                          int lane, int m_base, int n_base,
                                          float acc[2][4][4]) {
    const uint32_t aoff = (uint32_t)(m_base + (lane & 15)) * ROWB +
                          (uint32_t)(lane >> 4) * 16;
    const uint32_t a_hi = sbase + SA_HI + aoff;
    const uint32_t a_lo = sbase + SA_LO + aoff;
    const uint32_t boff =
        (uint32_t)(n_base + (lane & 7) + (((lane >> 4) & 1) << 3)) * ROWB +
        (uint32_t)((lane >> 3) & 1) * 16;
    const uint32_t b_hi = bbase + boff;
    const uint32_t b_lo = bbase + 25600u + boff;

    uint32_t ah[2][2][4], al[2][2][4], bh[2][2][4], bl[2][2][4];
    // preload ks=0 into buffer 0
    LDM4(ah[0][0], a_hi);
    LDM4(ah[0][1], a_hi + 16 * ROWB);
    LDM4(al[0][0], a_lo);
    LDM4(al[0][1], a_lo + 16 * ROWB);
    LDM4(bh[0][0], b_hi);
    LDM4(bh[0][1], b_hi + 16 * ROWB);
    LDM4(bl[0][0], b_lo);
    LDM4(bl[0][1], b_lo + 16 * ROWB);

#pragma unroll
    for (int ks = 0; ks < 12; ks++) {
        const int cur = ks & 1;
        const int nxt = cur ^ 1;
        if (ks < 11) {
            const uint32_t kb = (uint32_t)(ks + 1) * 32;
            LDM4(ah[nxt][0], a_hi + kb);
            LDM4(ah[nxt][1], a_hi + 16 * ROWB + kb);
            LDM4(al[nxt][0], a_lo + kb);
            LDM4(al[nxt][1], a_lo + 16 * ROWB + kb);
            LDM4(bh[nxt][0], b_hi + kb);
            LDM4(bh[nxt][1], b_hi + 16 * ROWB + kb);
            LDM4(bl[nxt][0], b_lo + kb);
            LDM4(bl[nxt][1], b_lo + 16 * ROWB + kb);
        }
#pragma unroll
        for (int mi = 0; mi < 2; mi++) {
#pragma unroll
            for (int ni = 0; ni < 4; ni++) {
                uint32_t bfh[2] = {bh[cur][ni >> 1][(ni & 1) * 2],
                                   bh[cur][ni >> 1][(ni & 1) * 2 + 1]};
                uint32_t bfl[2] = {bl[cur][ni >> 1][(ni & 1) * 2],
                                   bl[cur][ni >> 1][(ni & 1) * 2 + 1]};
                MMA16816(acc[mi][ni], ah[cur][mi], bfh);
                MMA16816(acc[mi][ni], al[cur][mi], bfh);
                MMA16816(acc[mi][ni], ah[cur][mi], bfl);
            }
        }
    }
}

// ---------------------------------------------------------------------------
// Kernel 0: weight pre-conversion into [n][k] bf16 hi/lo planes.
// ---------------------------------------------------------------------------
__global__ __launch_bounds__(256) void k_prep(
    const float* __restrict__ wq, const float* __restrict__ wl)
{
    const int idx = blockIdx.x * 256 + threadIdx.x;
    if (idx < 576 * 192) {
        const int n = idx / 192, k = idx - n * 192;
        const float v = wq[(size_t)k * 576 + n];
        const __nv_bfloat16 h = __float2bfloat16(v);
        g_wq_hi[idx] = h;
        g_wq_lo[idx] = __float2bfloat16(v - __bfloat162float(h));
    }
    if (idx < 192 * 192) {
        const int n = idx / 192, k = idx - n * 192;
        const float v = wl[(size_t)k * 192 + n];
        const __nv_bfloat16 h = __float2bfloat16(v);
        g_wl_hi[idx] = h;
        g_wl_lo[idx] = __float2bfloat16(v - __bfloat162float(h));
    }
}

// ---------------------------------------------------------------------------
// Kernel 1: QKV projection. Grid (2048), 256 threads (8 warps, 4m x 2n).
// ---------------------------------------------------------------------------
__global__ __launch_bounds__(256) void k_qkv(
    const float* __restrict__ x, const float* __restrict__ bias)
{
    extern __shared__ char sm[];
    const uint32_t sbase = smem_u32(sm);
    const int t    = threadIdx.x;
    const int lane = t & 31;
    const int wid  = t >> 5;
    const int mt   = blockIdx.x;

    stage_b_async(sbase + S_B, g_wq_hi, g_wq_lo, 0, t);
    CP_COMMIT();

    // --- stage A (128 tokens x 192 ch), shift fused, split hi/lo
    for (int idx4 = t; idx4 < 6144; idx4 += 256) {
        const int m  = idx4 / 48;
        const int k4 = idx4 % 48;
        const int win = mt * 2 + (m >> 6);
        const int b  = win >> 10, wy = (win >> 5) & 31, wx = win & 31;
        const int p  = m & 63;
        const int shh = ((wy << 3) + (p >> 3) + 4) & 255;
        const int sww = ((wx << 3) + (p & 7) + 4) & 255;
        const float4 v = *reinterpret_cast<const float4*>(
            x + ((((size_t)b << 8) + shh) * 256 + sww) * 192 + k4 * 4);
        const uint32_t off = (uint32_t)m * ROWB + k4 * 8;
        split_store4p(sm + SA_HI + off, sm + SA_LO + off, v);
    }

    const int m_base = (wid >> 1) * 32;
    const int n_base = (wid & 1) * 32;
    const int lane4 = lane >> 2;
    const int lane2 = (lane & 3) * 2;

    for (int nt = 0; nt < 9; nt++) {
        __syncthreads();
        if (nt < 8) {
            stage_b_async(sbase + S_B + ((nt + 1) & 1) * B_BUF,
                          g_wq_hi, g_wq_lo, (nt + 1) * 64, t);
            CP_COMMIT();
            CP_WAIT1();
        } else {
            CP_WAIT0();
        }
        __syncthreads();

        float acc[2][4][4] = {};
        gemm_body(sbase, sbase + S_B + (nt & 1) * B_BUF,
                  lane, m_base, n_base, acc);

        const int n0 = nt * 64;
#pragma unroll
        for (int mi = 0; mi < 2; mi++) {
            const int r  = m_base + mi * 16 + lane4;
            const int r2 = r + 8;
            const int win = mt * 2 + (r >> 6);
            const int p  = r & 63;
            const int p2 = r2 & 63;
#pragma unroll
            for (int ni = 0; ni < 4; ni++) {
                const int ng = n0 + n_base + ni * 8 + lane2;
                const int which = ng / 192;
                const int rr = ng - which * 192;
                const int head = rr >> 5;
                const int d = rr & 31;
                const float2 bb = *reinterpret_cast<const float2*>(bias + ng);
                float* gq = g_qkv + (size_t)which * QKV_STRIDE +
                            ((size_t)win * 6 + head) * 2048 + d;
                *reinterpret_cast<float2*>(gq + (size_t)p * 32) =
                    make_float2(acc[mi][ni][0] + bb.x, acc[mi][ni][1] + bb.y);
                *reinterpret_cast<float2*>(gq + (size_t)p2 * 32) =
                    make_float2(acc[mi][ni][2] + bb.x, acc[mi][ni][3] + bb.y);
            }
        }
    }
}

// ---------------------------------------------------------------------------
// Kernel 2: windowed attention (FFMA2). Grid (6144), 256 threads =
// 4 (win,head) pairs per block; dynamic smem 64KB.
// ---------------------------------------------------------------------------
__global__ __launch_bounds__(256) void k_attn(const float* __restrict__ rel_pos)
{
    extern __shared__ float smf[];
    const int t    = threadIdx.x;
    const int grp  = t >> 6;                 // 0..3
    const int p    = t & 63;
    const int pair = blockIdx.x * 4 + grp;   // win*6 + head
    const int win  = pair / 6;
    const int head = pair - win * 6;
    const int wy = (win >> 5) & 31;
    const int wx = win & 31;

    float* Ks = smf + grp * 4096;            // [64][32]
    float* Vs = Ks + 2048;

    const size_t base = (size_t)pair * 2048;
    const float* qb = g_qkv + base;
    const float* kb = g_qkv + QKV_STRIDE + base;
    const float* vb = g_qkv + 2 * QKV_STRIDE + base;

    ULL q2[16];
#pragma unroll
    for (int u = 0; u < 8; u++) {
        const ulonglong2 qv =
            *reinterpret_cast<const ulonglong2*>(qb + p * 32 + u * 4);
        q2[2 * u] = qv.x; q2[2 * u + 1] = qv.y;
        *reinterpret_cast<float4*>(Ks + p * 32 + u * 4) =
            *reinterpret_cast<const float4*>(kb + p * 32 + u * 4);
        *reinterpret_cast<float4*>(Vs + p * 32 + u * 4) =
            *reinterpret_cast<const float4*>(vb + p * 32 + u * 4);
    }
    __syncthreads();

    const int y1 = p >> 3, x1 = p & 7;
    const bool lastR = (wy == 31);
    const bool lastC = (wx == 31);

    float sc[64];
    float mx = -1e30f;
#pragma unroll 4
    for (int j = 0; j < 64; j++) {
        ULL s2a = 0ull, s2b = 0ull;
        const ulonglong2* kp = reinterpret_cast<const ulonglong2*>(Ks + j * 32);
#pragma unroll
        for (int u = 0; u < 8; u++) {
            const ulonglong2 kv = kp[u];
            s2a = fma2(q2[2 * u], kv.x, s2a);
            s2b = fma2(q2[2 * u + 1], kv.y, s2b);
        }
        float s = (lo2(s2a) + hi2(s2a)) + (lo2(s2b) + hi2(s2b));
        s *= 0.1767766953f;
        const int y2 = j >> 3, x2 = j & 7;
        s += rel_pos[((y1 - y2 + 7) * 15 + (x1 - x2 + 7)) * 6 + head];
        const bool bad = (lastR && ((y1 < 4) != (y2 < 4))) ||
                         (lastC && ((x1 < 4) != (x2 < 4)));
        if (bad) s = -1e30f;
        sc[j] = s;
        mx = fmaxf(mx, s);
    }
    float sum = 0.f;
#pragma unroll 4
    for (int j = 0; j < 64; j++) { sc[j] = __expf(sc[j] - mx); sum += sc[j]; }
    const float inv = 1.f / sum;

    ULL out2[16];
#pragma unroll
    for (int u = 0; u < 16; u++) out2[u] = 0ull;
#pragma unroll 4
    for (int j = 0; j < 64; j++) {
        const ULL wj = pack2(sc[j], sc[j]);
        const ulonglong2* vp = reinterpret_cast<const ulonglong2*>(Vs + j * 32);
#pragma unroll
        for (int u = 0; u < 8; u++) {
            const ulonglong2 vv = vp[u];
            out2[2 * u]     = fma2(wj, vv.x, out2[2 * u]);
            out2[2 * u + 1] = fma2(wj, vv.y, out2[2 * u + 1]);
        }
    }

    float* ob = g_attn + ((size_t)win * 64 + p) * 192 + head * 32;
#pragma unroll
    for (int u = 0; u < 8; u++) {
        float4 st;
        st.x = lo2(out2[2 * u])     * inv;
        st.y = hi2(out2[2 * u])     * inv;
        st.z = lo2(out2[2 * u + 1]) * inv;
        st.w = hi2(out2[2 * u + 1]) * inv;
        *reinterpret_cast<float4*>(ob + u * 4) = st;
    }
}

// ---------------------------------------------------------------------------
// Kernel 3: output projection. Grid (2048), 256 threads, loops 3 n-tiles.
// ---------------------------------------------------------------------------
__global__ __launch_bounds__(256) void k_proj(
    const float* __restrict__ bias, float* __restrict__ out)
{
    extern __shared__ char sm[];
    const uint32_t sbase = smem_u32(sm);
    const int t    = threadIdx.x;
    const int lane = t & 31;
    const int wid  = t >> 5;
    const int mt   = blockIdx.x;

    stage_b_async(sbase + S_B, g_wl_hi, g_wl_lo, 0, t);
    CP_COMMIT();

    const float* abase = g_attn + (size_t)mt * 128 * 192;
    for (int idx4 = t; idx4 < 6144; idx4 += 256) {
        const int m  = idx4 / 48;
        const int k4 = idx4 % 48;
        const float4 v = *reinterpret_cast<const float4*>(abase + m * 192 + k4 * 4);
        const uint32_t off = (uint32_t)m * ROWB + k4 * 8;
        split_store4p(sm + SA_HI + off, sm + SA_LO + off, v);
    }

    const int m_base = (wid >> 1) * 32;
    const int n_base = (wid & 1) * 32;
    const int lane4 = lane >> 2;
    const int lane2 = (lane & 3) * 2;

    for (int nt = 0; nt < 3; nt++) {
        __syncthreads();
        if (nt < 2) {
            stage_b_async(sbase + S_B + ((nt + 1) & 1) * B_BUF,
                          g_wl_hi, g_wl_lo, (nt + 1) * 64, t);
            CP_COMMIT();
            CP_WAIT1();
        } else {
            CP_WAIT0();
        }
        __syncthreads();

        float acc[2][4][4] = {};
        gemm_body(sbase, sbase + S_B + (nt & 1) * B_BUF,
                  lane, m_base, n_base, acc);

        const int n0 = nt * 64;
#pragma unroll
        for (int mi = 0; mi < 2; mi++) {
#pragma unroll
            for (int half = 0; half < 2; half++) {
                const int r = m_base + mi * 16 + half * 8 + lane4;
                const int win = mt * 2 + (r >> 6);
                const int b  = win >> 10;
                const int wy = (win >> 5) & 31;
                const int wx = win & 31;
                const int p  = r & 63;
                const int oh = ((wy << 3) + (p >> 3) + 4) & 255;
                const int ow = ((wx << 3) + (p & 7) + 4) & 255;
                float* orow = out + ((((size_t)b << 8) + oh) * 256 + ow) * 192;
#pragma unroll
                for (int ni = 0; ni < 4; ni++) {
                    const int ng = n0 + n_base + ni * 8 + lane2;
                    const float2 bb = *reinterpret_cast<const float2*>(bias + ng);
                    float2 st;
                    st.x = acc[mi][ni][half * 2 + 0] + bb.x;
                    st.y = acc[mi][ni][half * 2 + 1] + bb.y;
                    *reinterpret_cast<float2*>(orow + ng) = st;
                }
            }
        }
    }
}

// ---------------------------------------------------------------------------
extern "C" void kernel_launch(void* const* d_in, const int* in_sizes, int n_in,
                              void* d_out, int out_size)
{
    const float* x     = (const float*)d_in[0];
    const float* w_qkv = (const float*)d_in[1];
    const float* b_qkv = (const float*)d_in[2];
    const float* w_lin = (const float*)d_in[3];
    const float* b_lin = (const float*)d_in[4];
    const float* rel   = (const float*)d_in[5];
    float* out = (float*)d_out;

    cudaFuncSetAttribute(k_qkv, cudaFuncAttributeMaxDynamicSharedMemorySize, SMEM_SZ);
    cudaFuncSetAttribute(k_proj, cudaFuncAttributeMaxDynamicSharedMemorySize, SMEM_SZ);
    cudaFuncSetAttribute(k_attn, cudaFuncAttributeMaxDynamicSharedMemorySize, 65536);

    k_prep<<<432, 256>>>(w_qkv, w_lin);
    k_qkv <<<2048, 256, SMEM_SZ>>>(x, b_qkv);
    k_attn<<<6144, 256, 65536>>>(rel);
    k_proj<<<2048, 256, SMEM_SZ>>>(b_lin, out);
}